// round 1
// baseline (speedup 1.0000x reference)
#include <cuda_runtime.h>
#include <math.h>

// Problem constants
#define BB 2
#define SS 4096
#define HH 2048
#define DD 2048
#define ND 6144   // 3*D

// ---------------------------------------------------------------------------
// Scratch (allocation-free: __device__ globals)
// ---------------------------------------------------------------------------
__device__ float g_xnorm[(size_t)BB * SS * HH];          //  64 MB
__device__ float g_qkv  [(size_t)BB * SS * ND];          // 192 MB
__device__ float g_scores[(size_t)BB * SS * SS];         // 128 MB (reused in-place for probs)
__device__ float g_attn [(size_t)BB * SS * DD];          //  64 MB

// ---------------------------------------------------------------------------
// LayerNorm: one block per row of 2048
// ---------------------------------------------------------------------------
__global__ void __launch_bounds__(256) ln_kernel(const float* __restrict__ x,
                                                 float* __restrict__ xn)
{
    int row = blockIdx.x;
    const float4* xr = (const float4*)(x + (size_t)row * HH);
    float4*       yr = (float4*)(xn + (size_t)row * HH);
    int tid = threadIdx.x;

    float4 v0 = xr[tid];
    float4 v1 = xr[tid + 256];

    float s  = v0.x + v0.y + v0.z + v0.w + v1.x + v1.y + v1.z + v1.w;
    float sq = v0.x*v0.x + v0.y*v0.y + v0.z*v0.z + v0.w*v0.w
             + v1.x*v1.x + v1.y*v1.y + v1.z*v1.z + v1.w*v1.w;

    // block reduce (8 warps)
    __shared__ float rs[8], rq[8];
    #pragma unroll
    for (int o = 16; o > 0; o >>= 1) {
        s  += __shfl_xor_sync(0xffffffffu, s,  o);
        sq += __shfl_xor_sync(0xffffffffu, sq, o);
    }
    if ((tid & 31) == 0) { rs[tid >> 5] = s; rq[tid >> 5] = sq; }
    __syncthreads();
    float ts = 0.f, tq = 0.f;
    #pragma unroll
    for (int i = 0; i < 8; i++) { ts += rs[i]; tq += rq[i]; }

    float mean = ts * (1.0f / HH);
    float var  = tq * (1.0f / HH) - mean * mean;
    float rstd = rsqrtf(var + 1e-6f);

    float4 o0, o1;
    o0.x = (v0.x - mean) * rstd; o0.y = (v0.y - mean) * rstd;
    o0.z = (v0.z - mean) * rstd; o0.w = (v0.w - mean) * rstd;
    o1.x = (v1.x - mean) * rstd; o1.y = (v1.y - mean) * rstd;
    o1.z = (v1.z - mean) * rstd; o1.w = (v1.w - mean) * rstd;
    yr[tid]       = o0;
    yr[tid + 256] = o1;
}

// ---------------------------------------------------------------------------
// Generic tiled SGEMM: C[M,N] = A[M,K] @ op(B) (+ residual)
//   TB=false : B is K x N row-major (ldb)
//   TB=true  : B is N x K row-major (ldb)  => C = A @ B^T
//   CAUSAL   : skip blocks strictly above diagonal (BM==BN)
//   RES      : C += Resid (same layout/ld as C)
// Batched over blockIdx.z with element strides sAz/sBz/sCz.
// All dims assumed divisible by tile sizes (true for this problem).
// ---------------------------------------------------------------------------
template<bool TB, bool RES, bool CAUSAL>
__global__ void __launch_bounds__(256) sgemm_kernel(
    const float* __restrict__ A, const float* __restrict__ B,
    float* __restrict__ C, const float* __restrict__ Resid,
    int K, int lda, int ldb, int ldc,
    size_t sAz, size_t sBz, size_t sCz)
{
    constexpr int BM = 128, BN = 128, BK = 16;
    const int bx = blockIdx.x, by = blockIdx.y, bz = blockIdx.z;
    if (CAUSAL && bx > by) return;

    A += (size_t)bz * sAz;
    B += (size_t)bz * sBz;
    C += (size_t)bz * sCz;

    const int r0 = by * BM, c0 = bx * BN;
    const int tid = threadIdx.x;
    const int tx = tid & 15, ty = tid >> 4;

    __shared__ float As[BK][BM + 4];
    __shared__ float Bs[BK][BN + 4];

    float acc[8][8];
    #pragma unroll
    for (int i = 0; i < 8; i++)
        #pragma unroll
        for (int j = 0; j < 8; j++) acc[i][j] = 0.f;

    // A-load mapping: 64 rows per pass, float4 along K
    const int aRow = tid >> 2;          // 0..63
    const int aCol = (tid & 3) << 2;    // 0,4,8,12
    // B-load mapping (NN): 8 K-rows per pass, float4 along N
    const int bRowN = tid >> 5;         // 0..7
    const int bColN = (tid & 31) << 2;  // 0..124
    // B-load mapping (NT): 64 N-rows per pass, float4 along K
    const int bN = tid >> 2;            // 0..63
    const int bK = (tid & 3) << 2;      // 0,4,8,12

    for (int k0 = 0; k0 < K; k0 += BK) {
        #pragma unroll
        for (int r = 0; r < 2; r++) {
            float4 va = *(const float4*)(A + (size_t)(r0 + aRow + r * 64) * lda + k0 + aCol);
            As[aCol + 0][aRow + r * 64] = va.x;
            As[aCol + 1][aRow + r * 64] = va.y;
            As[aCol + 2][aRow + r * 64] = va.z;
            As[aCol + 3][aRow + r * 64] = va.w;
        }
        if (!TB) {
            #pragma unroll
            for (int r = 0; r < 2; r++) {
                float4 vb = *(const float4*)(B + (size_t)(k0 + bRowN + r * 8) * ldb + c0 + bColN);
                *(float4*)&Bs[bRowN + r * 8][bColN] = vb;
            }
        } else {
            #pragma unroll
            for (int r = 0; r < 2; r++) {
                float4 vb = *(const float4*)(B + (size_t)(c0 + bN + r * 64) * ldb + k0 + bK);
                Bs[bK + 0][bN + r * 64] = vb.x;
                Bs[bK + 1][bN + r * 64] = vb.y;
                Bs[bK + 2][bN + r * 64] = vb.z;
                Bs[bK + 3][bN + r * 64] = vb.w;
            }
        }
        __syncthreads();

        #pragma unroll
        for (int k = 0; k < BK; k++) {
            float4 a0 = *(const float4*)&As[k][ty * 8];
            float4 a1 = *(const float4*)&As[k][ty * 8 + 4];
            float4 b0 = *(const float4*)&Bs[k][tx * 8];
            float4 b1 = *(const float4*)&Bs[k][tx * 8 + 4];
            float av[8] = {a0.x, a0.y, a0.z, a0.w, a1.x, a1.y, a1.z, a1.w};
            float bv[8] = {b0.x, b0.y, b0.z, b0.w, b1.x, b1.y, b1.z, b1.w};
            #pragma unroll
            for (int i = 0; i < 8; i++)
                #pragma unroll
                for (int j = 0; j < 8; j++)
                    acc[i][j] = fmaf(av[i], bv[j], acc[i][j]);
        }
        __syncthreads();
    }

    // epilogue
    #pragma unroll
    for (int i = 0; i < 8; i++) {
        const int row = r0 + ty * 8 + i;
        float* crow = C + (size_t)row * ldc + c0 + tx * 8;
        #pragma unroll
        for (int jb = 0; jb < 2; jb++) {
            float4 o;
            o.x = acc[i][jb * 4 + 0];
            o.y = acc[i][jb * 4 + 1];
            o.z = acc[i][jb * 4 + 2];
            o.w = acc[i][jb * 4 + 3];
            if (RES) {
                const float4 rv = *(const float4*)(Resid + (size_t)row * ldc + c0 + tx * 8 + jb * 4);
                o.x += rv.x; o.y += rv.y; o.z += rv.z; o.w += rv.w;
            }
            *(float4*)(crow + jb * 4) = o;
        }
    }
}

// ---------------------------------------------------------------------------
// Causal softmax, in-place on scores. Row r uses cols [0, r]; zeros the rest
// so the PV GEMM can run dense.
// ---------------------------------------------------------------------------
__global__ void __launch_bounds__(256) softmax_kernel(float* __restrict__ scores,
                                                      float scale)
{
    const int r = blockIdx.x;
    const int b = blockIdx.y;
    float* row = scores + ((size_t)b * SS + r) * SS;
    const int len = r + 1;
    const int tid = threadIdx.x;

    __shared__ float buf[SS];
    __shared__ float red[8];

    float lmax = -1e30f;
    for (int t = tid; t < len; t += 256) {
        float v = row[t] * scale;
        buf[t] = v;
        lmax = fmaxf(lmax, v);
    }
    #pragma unroll
    for (int o = 16; o > 0; o >>= 1)
        lmax = fmaxf(lmax, __shfl_xor_sync(0xffffffffu, lmax, o));
    if ((tid & 31) == 0) red[tid >> 5] = lmax;
    __syncthreads();
    float m = -1e30f;
    #pragma unroll
    for (int i = 0; i < 8; i++) m = fmaxf(m, red[i]);
    __syncthreads();

    float lsum = 0.f;
    for (int t = tid; t < len; t += 256) {
        float e = expf(buf[t] - m);
        buf[t] = e;
        lsum += e;
    }
    #pragma unroll
    for (int o = 16; o > 0; o >>= 1)
        lsum += __shfl_xor_sync(0xffffffffu, lsum, o);
    if ((tid & 31) == 0) red[tid >> 5] = lsum;
    __syncthreads();
    float tot = 0.f;
    #pragma unroll
    for (int i = 0; i < 8; i++) tot += red[i];
    const float inv = 1.0f / tot;

    for (int t = tid; t < len; t += 256) row[t] = buf[t] * inv;
    for (int t = len + tid; t < SS; t += 256) row[t] = 0.f;
}

// ---------------------------------------------------------------------------
// Launch
// ---------------------------------------------------------------------------
extern "C" void kernel_launch(void* const* d_in, const int* in_sizes, int n_in,
                              void* d_out, int out_size)
{
    (void)in_sizes; (void)n_in; (void)out_size;
    const float* x     = (const float*)d_in[0];   // (2, 4096, 2048)
    const float* qkvW  = (const float*)d_in[1];   // (2048, 6144)
    const float* oproj = (const float*)d_in[2];   // (2048, 2048)
    float* out = (float*)d_out;                   // (2, 4096, 2048)

    float *xn, *qk, *sc, *at;
    cudaGetSymbolAddress((void**)&xn, g_xnorm);
    cudaGetSymbolAddress((void**)&qk, g_qkv);
    cudaGetSymbolAddress((void**)&sc, g_scores);
    cudaGetSymbolAddress((void**)&at, g_attn);

    const int M = BB * SS;                 // 8192
    const float scale = 1.0f / sqrtf((float)DD);

    // 1) LayerNorm
    ln_kernel<<<M, 256>>>(x, xn);

    // 2) QKV GEMM: (8192 x 2048) @ (2048 x 6144) -> g_qkv
    sgemm_kernel<false, false, false><<<dim3(ND / 128, M / 128, 1), 256>>>(
        xn, qkvW, qk, nullptr, HH, HH, ND, ND, 0, 0, 0);

    // 3) Scores = Q @ K^T (NT, causal skip), per batch via z
    sgemm_kernel<true, false, true><<<dim3(SS / 128, SS / 128, BB), 256>>>(
        qk, qk + DD, sc, nullptr, DD, ND, ND, SS,
        (size_t)SS * ND, (size_t)SS * ND, (size_t)SS * SS);

    // 4) Causal softmax (in-place, zeros above diagonal)
    softmax_kernel<<<dim3(SS, BB), 256>>>(sc, scale);

    // 5) Attn = P @ V  (NN), per batch
    sgemm_kernel<false, false, false><<<dim3(DD / 128, SS / 128, BB), 256>>>(
        sc, qk + 2 * DD, at, nullptr, SS, SS, ND, DD,
        (size_t)SS * SS, (size_t)SS * ND, (size_t)SS * DD);

    // 6) Out = Attn @ o_proj + x
    sgemm_kernel<false, true, false><<<dim3(HH / 128, M / 128, 1), 256>>>(
        at, oproj, out, x, DD, DD, HH, HH, 0, 0, 0);
}

// round 3
// speedup vs baseline: 3.5658x; 3.5658x over previous
#include <cuda_runtime.h>
#include <math.h>
#include <stdint.h>

// Problem constants
#define BB 2
#define SS 4096
#define HH 2048
#define DD 2048
#define ND 6144   // 3*D

// ---------------------------------------------------------------------------
// Scratch (allocation-free: __device__ globals)
// ---------------------------------------------------------------------------
__device__ float g_xnorm [(size_t)BB * SS * HH];   //  64 MB (tf32-rounded)
__device__ float g_qkv   [(size_t)BB * SS * ND];   // 192 MB (tf32-rounded)
__device__ float g_scores[(size_t)BB * SS * SS];   // 128 MB
__device__ float g_attn  [(size_t)BB * SS * DD];   //  64 MB (tf32-rounded)
__device__ float g_qkvT  [(size_t)ND * HH];        //  48 MB (tf32-rounded)
__device__ float g_oprojT[(size_t)HH * DD];        //  16 MB (tf32-rounded)
__device__ float g_vT    [(size_t)BB * DD * SS];   //  64 MB (tf32-rounded)

// ---------------------------------------------------------------------------
// Helpers
// ---------------------------------------------------------------------------
__device__ __forceinline__ uint32_t smem_u32(const void* p) {
    uint32_t a;
    asm("{ .reg .u64 t; cvta.to.shared.u64 t, %1; cvt.u32.u64 %0, t; }" : "=r"(a) : "l"(p));
    return a;
}

__device__ __forceinline__ float to_tf32(float x) {
    uint32_t u;
    asm("cvt.rna.tf32.f32 %0, %1;" : "=r"(u) : "f"(x));
    return __uint_as_float(u);
}

__device__ __forceinline__ void cp_async16(uint32_t smem, const void* glob) {
    asm volatile("cp.async.cg.shared.global [%0], [%1], 16;" :: "r"(smem), "l"(glob));
}

__device__ __forceinline__ void mma_tf32(float* c, const uint32_t* a, const uint32_t* b) {
    asm volatile(
        "mma.sync.aligned.m16n8k8.row.col.f32.tf32.tf32.f32 "
        "{%0,%1,%2,%3}, {%4,%5,%6,%7}, {%8,%9}, {%0,%1,%2,%3};"
        : "+f"(c[0]), "+f"(c[1]), "+f"(c[2]), "+f"(c[3])
        : "r"(a[0]), "r"(a[1]), "r"(a[2]), "r"(a[3]), "r"(b[0]), "r"(b[1]));
}

// ---------------------------------------------------------------------------
// LayerNorm (tf32-rounded output)
// ---------------------------------------------------------------------------
__global__ void __launch_bounds__(256) ln_kernel(const float* __restrict__ x,
                                                 float* __restrict__ xn)
{
    int row = blockIdx.x;
    const float4* xr = (const float4*)(x + (size_t)row * HH);
    float4*       yr = (float4*)(xn + (size_t)row * HH);
    int tid = threadIdx.x;

    float4 v0 = xr[tid];
    float4 v1 = xr[tid + 256];
    float s  = v0.x + v0.y + v0.z + v0.w + v1.x + v1.y + v1.z + v1.w;
    float sq = v0.x*v0.x + v0.y*v0.y + v0.z*v0.z + v0.w*v0.w
             + v1.x*v1.x + v1.y*v1.y + v1.z*v1.z + v1.w*v1.w;

    __shared__ float rs[8], rq[8];
    #pragma unroll
    for (int o = 16; o > 0; o >>= 1) {
        s  += __shfl_xor_sync(0xffffffffu, s,  o);
        sq += __shfl_xor_sync(0xffffffffu, sq, o);
    }
    if ((tid & 31) == 0) { rs[tid >> 5] = s; rq[tid >> 5] = sq; }
    __syncthreads();
    float ts = 0.f, tq = 0.f;
    #pragma unroll
    for (int i = 0; i < 8; i++) { ts += rs[i]; tq += rq[i]; }

    float mean = ts * (1.0f / HH);
    float var  = tq * (1.0f / HH) - mean * mean;
    float rstd = rsqrtf(var + 1e-6f);

    float4 o0, o1;
    o0.x = to_tf32((v0.x - mean) * rstd); o0.y = to_tf32((v0.y - mean) * rstd);
    o0.z = to_tf32((v0.z - mean) * rstd); o0.w = to_tf32((v0.w - mean) * rstd);
    o1.x = to_tf32((v1.x - mean) * rstd); o1.y = to_tf32((v1.y - mean) * rstd);
    o1.z = to_tf32((v1.z - mean) * rstd); o1.w = to_tf32((v1.w - mean) * rstd);
    yr[tid]       = o0;
    yr[tid + 256] = o1;
}

// ---------------------------------------------------------------------------
// Tiled transpose: out[c*ldo + r] = tf32round(in[r*ldi + c])
// ---------------------------------------------------------------------------
__global__ void __launch_bounds__(256) transpose_kernel(
    const float* __restrict__ in, float* __restrict__ out,
    int ldi, int ldo, size_t sIz, size_t sOz)
{
    __shared__ float t[32][33];
    in  += (size_t)blockIdx.z * sIz;
    out += (size_t)blockIdx.z * sOz;
    int tx = threadIdx.x & 31, ty = threadIdx.x >> 5;   // 32 x 8
    int c = blockIdx.x * 32 + tx;
    int r = blockIdx.y * 32 + ty;
    #pragma unroll
    for (int j = 0; j < 4; j++)
        t[ty + 8 * j][tx] = in[(size_t)(r + 8 * j) * ldi + c];
    __syncthreads();
    int co = blockIdx.y * 32 + tx;
    int ro = blockIdx.x * 32 + ty;
    #pragma unroll
    for (int j = 0; j < 4; j++)
        out[(size_t)(ro + 8 * j) * ldo + co] = to_tf32(t[tx][ty + 8 * j]);
}

// ---------------------------------------------------------------------------
// tf32 mma.sync NT GEMM: C[M,N] = A[M,K] @ B[N,K]^T (both K-major row-major)
// BM=BN=128, BK=32, 256 threads, double-buffered cp.async.
// Warp grid 2(M)x4(N): warp tile 64x32. Fragments per PTX m16n8k8 tf32 layout.
// Smem rows stride BK+4=36 floats (≡4 banks) => conflict-free fragment gathers.
// ---------------------------------------------------------------------------
#define BM 128
#define BN 128
#define BK 32
#define LDSK (BK + 4)                         // 36 floats
#define STAGE_FLOATS (BM * LDSK + BN * LDSK)  // 9216
#define GEMM_DYN_SMEM (2 * STAGE_FLOATS * 4)  // 73728 B

template<bool CAUSAL, bool RES, bool ROUND>
__global__ void __launch_bounds__(256, 2) mma_gemm(
    const float* __restrict__ A, const float* __restrict__ B,
    float* __restrict__ C, const float* __restrict__ Resid,
    int K, int lda, int ldb, int ldc,
    size_t sAz, size_t sBz, size_t sCz)
{
    const int bx = blockIdx.x, by = blockIdx.y, bz = blockIdx.z;
    if (CAUSAL && bx > by) return;

    extern __shared__ float sm[];

    const int tid = threadIdx.x;
    const int wid = tid >> 5, lane = tid & 31;
    const int qid = lane >> 2;     // 0..7
    const int tq  = lane & 3;      // 0..3
    const int wm = (wid & 1) * 64; // warp M offset in tile
    const int wn = (wid >> 1) * 32;

    const float* Ab = A + (size_t)bz * sAz + (size_t)(by * BM) * lda;
    const float* Bb = B + (size_t)bz * sBz + (size_t)(bx * BN) * ldb;

    // cp.async mapping: 8 float4 per row, 128 rows, 256 threads -> 4 each per tile
    const int ldRow = tid >> 3;        // 0..31 base; +32*i
    const int ldCh  = (tid & 7) * 4;   // float offset 0,4,...,28

    float acc[4][4][4];
    #pragma unroll
    for (int i = 0; i < 4; i++)
        #pragma unroll
        for (int j = 0; j < 4; j++)
            #pragma unroll
            for (int h = 0; h < 4; h++) acc[i][j][h] = 0.f;

    const int nk = K / BK;

    // stage loader
    auto load_stage = [&](int kt, int s) {
        const int k0 = kt * BK;
        float* as = sm + s * STAGE_FLOATS;
        float* bs = as + BM * LDSK;
        #pragma unroll
        for (int i = 0; i < 4; i++) {
            int row = ldRow + 32 * i;
            cp_async16(smem_u32(as + row * LDSK + ldCh),
                       Ab + (size_t)row * lda + k0 + ldCh);
        }
        #pragma unroll
        for (int i = 0; i < 4; i++) {
            int row = ldRow + 32 * i;
            cp_async16(smem_u32(bs + row * LDSK + ldCh),
                       Bb + (size_t)row * ldb + k0 + ldCh);
        }
        asm volatile("cp.async.commit_group;" ::: "memory");
    };

    load_stage(0, 0);

    for (int kt = 0; kt < nk; kt++) {
        const int s = kt & 1;
        if (kt + 1 < nk) {
            load_stage(kt + 1, s ^ 1);
            asm volatile("cp.async.wait_group 1;" ::: "memory");
        } else {
            asm volatile("cp.async.wait_group 0;" ::: "memory");
        }
        __syncthreads();

        const float* as = sm + s * STAGE_FLOATS;
        const float* bs = as + BM * LDSK;
        #pragma unroll
        for (int ks = 0; ks < 4; ks++) {
            const int k = ks * 8;
            uint32_t a[4][4], b[4][2];
            #pragma unroll
            for (int mt = 0; mt < 4; mt++) {
                const float* ap = as + (wm + mt * 16 + qid) * LDSK + k + tq;
                a[mt][0] = __float_as_uint(ap[0]);
                a[mt][1] = __float_as_uint(ap[8 * LDSK]);
                a[mt][2] = __float_as_uint(ap[4]);
                a[mt][3] = __float_as_uint(ap[8 * LDSK + 4]);
            }
            #pragma unroll
            for (int nt = 0; nt < 4; nt++) {
                const float* bp = bs + (wn + nt * 8 + qid) * LDSK + k + tq;
                b[nt][0] = __float_as_uint(bp[0]);
                b[nt][1] = __float_as_uint(bp[4]);
            }
            #pragma unroll
            for (int mt = 0; mt < 4; mt++)
                #pragma unroll
                for (int nt = 0; nt < 4; nt++)
                    mma_tf32(acc[mt][nt], a[mt], b[nt]);
        }
        __syncthreads();
    }

    // epilogue
    C += (size_t)bz * sCz;
    const int crow0 = by * BM + wm;
    const int ccol0 = bx * BN + wn;
    #pragma unroll
    for (int mt = 0; mt < 4; mt++) {
        #pragma unroll
        for (int h = 0; h < 2; h++) {
            const int row = crow0 + mt * 16 + qid + h * 8;
            float* cr = C + (size_t)row * ldc;
            const float* rr = RES ? (Resid + (size_t)bz * sCz + (size_t)row * ldc) : nullptr;
            #pragma unroll
            for (int nt = 0; nt < 4; nt++) {
                const int col = ccol0 + nt * 8 + tq * 2;
                float2 v;
                v.x = acc[mt][nt][2 * h + 0];
                v.y = acc[mt][nt][2 * h + 1];
                if (RES) {
                    const float2 rv = *(const float2*)(rr + col);
                    v.x += rv.x; v.y += rv.y;
                }
                if (ROUND) { v.x = to_tf32(v.x); v.y = to_tf32(v.y); }
                *(float2*)(cr + col) = v;
            }
        }
    }
}

// ---------------------------------------------------------------------------
// Causal softmax, in-place; output tf32-rounded (feeds PV MMA)
// ---------------------------------------------------------------------------
__global__ void __launch_bounds__(256) softmax_kernel(float* __restrict__ scores,
                                                      float scale)
{
    const int r = blockIdx.x;
    const int b = blockIdx.y;
    float* row = scores + ((size_t)b * SS + r) * SS;
    const int len = r + 1;
    const int tid = threadIdx.x;

    __shared__ float buf[SS];
    __shared__ float red[8];

    float lmax = -1e30f;
    for (int t = tid; t < len; t += 256) {
        float v = row[t] * scale;
        buf[t] = v;
        lmax = fmaxf(lmax, v);
    }
    #pragma unroll
    for (int o = 16; o > 0; o >>= 1)
        lmax = fmaxf(lmax, __shfl_xor_sync(0xffffffffu, lmax, o));
    if ((tid & 31) == 0) red[tid >> 5] = lmax;
    __syncthreads();
    float m = -1e30f;
    #pragma unroll
    for (int i = 0; i < 8; i++) m = fmaxf(m, red[i]);
    __syncthreads();

    float lsum = 0.f;
    for (int t = tid; t < len; t += 256) {
        float e = expf(buf[t] - m);
        buf[t] = e;
        lsum += e;
    }
    #pragma unroll
    for (int o = 16; o > 0; o >>= 1)
        lsum += __shfl_xor_sync(0xffffffffu, lsum, o);
    if ((tid & 31) == 0) red[tid >> 5] = lsum;
    __syncthreads();
    float tot = 0.f;
    #pragma unroll
    for (int i = 0; i < 8; i++) tot += red[i];
    const float inv = 1.0f / tot;

    for (int t = tid; t < len; t += 256) row[t] = to_tf32(buf[t] * inv);
    for (int t = len + tid; t < SS; t += 256) row[t] = 0.f;
}

// ---------------------------------------------------------------------------
// Launch
// ---------------------------------------------------------------------------
extern "C" void kernel_launch(void* const* d_in, const int* in_sizes, int n_in,
                              void* d_out, int out_size)
{
    (void)in_sizes; (void)n_in; (void)out_size;
    const float* x     = (const float*)d_in[0];   // (2, 4096, 2048)
    const float* qkvW  = (const float*)d_in[1];   // (2048, 6144)
    const float* oproj = (const float*)d_in[2];   // (2048, 2048)
    float* out = (float*)d_out;                   // (2, 4096, 2048)

    float *xn, *qk, *sc, *at, *qT, *oT, *vT;
    cudaGetSymbolAddress((void**)&xn, g_xnorm);
    cudaGetSymbolAddress((void**)&qk, g_qkv);
    cudaGetSymbolAddress((void**)&sc, g_scores);
    cudaGetSymbolAddress((void**)&at, g_attn);
    cudaGetSymbolAddress((void**)&qT, g_qkvT);
    cudaGetSymbolAddress((void**)&oT, g_oprojT);
    cudaGetSymbolAddress((void**)&vT, g_vT);

    cudaFuncSetAttribute(mma_gemm<false, false, true>,
                         cudaFuncAttributeMaxDynamicSharedMemorySize, GEMM_DYN_SMEM);
    cudaFuncSetAttribute(mma_gemm<true, false, false>,
                         cudaFuncAttributeMaxDynamicSharedMemorySize, GEMM_DYN_SMEM);
    cudaFuncSetAttribute(mma_gemm<false, true, false>,
                         cudaFuncAttributeMaxDynamicSharedMemorySize, GEMM_DYN_SMEM);

    const int M = BB * SS;                 // 8192
    const float scale = 1.0f / sqrtf((float)DD);

    // 1) LayerNorm (tf32-rounded)
    ln_kernel<<<M, 256>>>(x, xn);

    // 2) Weight transposes (tf32-rounded)
    transpose_kernel<<<dim3(ND / 32, HH / 32, 1), 256>>>(qkvW, qT, ND, HH, 0, 0);
    transpose_kernel<<<dim3(HH / 32, DD / 32, 1), 256>>>(oproj, oT, HH, DD, 0, 0);

    // 3) QKV GEMM: xn[8192,2048] @ qT[6144,2048]^T -> qkv[8192,6144]
    mma_gemm<false, false, true><<<dim3(ND / BN, M / BM, 1), 256, GEMM_DYN_SMEM>>>(
        xn, qT, qk, nullptr, HH, HH, HH, ND, 0, 0, 0);

    // 4) V transpose: V[b][4096,2048] (ld=6144) -> vT[b][2048,4096]
    transpose_kernel<<<dim3(DD / 32, SS / 32, BB), 256>>>(
        qk + 2 * DD, vT, ND, SS, (size_t)SS * ND, (size_t)DD * SS);

    // 5) Scores = Q @ K^T (both K-major in g_qkv), causal block-skip
    mma_gemm<true, false, false><<<dim3(SS / BN, SS / BM, BB), 256, GEMM_DYN_SMEM>>>(
        qk, qk + DD, sc, nullptr, DD, ND, ND, SS,
        (size_t)SS * ND, (size_t)SS * ND, (size_t)SS * SS);

    // 6) Causal softmax (scale + mask + normalize + zero upper, tf32-rounded)
    softmax_kernel<<<dim3(SS, BB), 256>>>(sc, scale);

    // 7) Attn = P[4096,4096] @ vT[2048,4096]^T -> attn[4096,2048]
    mma_gemm<false, false, true><<<dim3(DD / BN, SS / BM, BB), 256, GEMM_DYN_SMEM>>>(
        sc, vT, at, nullptr, SS, SS, SS, DD,
        (size_t)SS * SS, (size_t)DD * SS, (size_t)SS * DD);

    // 8) Out = attn[8192,2048] @ oT[2048,2048]^T + x
    mma_gemm<false, true, false><<<dim3(HH / BN, M / BM, 1), 256, GEMM_DYN_SMEM>>>(
        at, oT, out, x, DD, DD, DD, HH, 0, 0, 0);
}

// round 4
// speedup vs baseline: 5.4377x; 1.5249x over previous
#include <cuda_runtime.h>
#include <cuda_fp16.h>
#include <math.h>
#include <stdint.h>

// Problem constants
#define BB 2
#define SS 4096
#define HH 2048
#define DD 2048
#define ND 6144   // 3*D

// ---------------------------------------------------------------------------
// Scratch (allocation-free: __device__ globals)
// ---------------------------------------------------------------------------
__device__ __half g_xh [(size_t)BB * SS * HH];    //  32 MB  LN output
__device__ __half g_qh [(size_t)BB * SS * ND];    //  96 MB  QKV output (Q,K,V)
__device__ float  g_sc [(size_t)BB * SS * SS];    // 128 MB  scores (fp32)
__device__ __half g_ph [(size_t)BB * SS * SS];    //  64 MB  probs (half)
__device__ __half g_ah [(size_t)BB * SS * DD];    //  32 MB  attn out
__device__ __half g_qTh[(size_t)ND * HH];         //  24 MB  qkv weight^T
__device__ __half g_oTh[(size_t)HH * DD];         //   8 MB  o_proj^T
__device__ __half g_vTh[(size_t)BB * DD * SS];    //  32 MB  V^T

// ---------------------------------------------------------------------------
// Helpers
// ---------------------------------------------------------------------------
__device__ __forceinline__ uint32_t smem_u32(const void* p) {
    uint32_t a;
    asm("{ .reg .u64 t; cvta.to.shared.u64 t, %1; cvt.u32.u64 %0, t; }" : "=r"(a) : "l"(p));
    return a;
}

__device__ __forceinline__ void cp_async16(uint32_t smem, const void* glob) {
    asm volatile("cp.async.cg.shared.global [%0], [%1], 16;" :: "r"(smem), "l"(glob));
}

__device__ __forceinline__ void ldmatrix_x4(uint32_t* r, uint32_t addr) {
    asm volatile("ldmatrix.sync.aligned.m8n8.x4.shared.b16 {%0,%1,%2,%3}, [%4];"
                 : "=r"(r[0]), "=r"(r[1]), "=r"(r[2]), "=r"(r[3]) : "r"(addr));
}

__device__ __forceinline__ void mma_f16(float* c, const uint32_t* a, const uint32_t* b) {
    asm volatile(
        "mma.sync.aligned.m16n8k16.row.col.f32.f16.f16.f32 "
        "{%0,%1,%2,%3}, {%4,%5,%6,%7}, {%8,%9}, {%0,%1,%2,%3};"
        : "+f"(c[0]), "+f"(c[1]), "+f"(c[2]), "+f"(c[3])
        : "r"(a[0]), "r"(a[1]), "r"(a[2]), "r"(a[3]), "r"(b[0]), "r"(b[1]));
}

// ---------------------------------------------------------------------------
// LayerNorm: fp32 in -> half out
// ---------------------------------------------------------------------------
__global__ void __launch_bounds__(256) ln_kernel(const float* __restrict__ x,
                                                 __half* __restrict__ xh)
{
    int row = blockIdx.x;
    const float4* xr = (const float4*)(x + (size_t)row * HH);
    __half2* yh = (__half2*)(xh + (size_t)row * HH);
    int tid = threadIdx.x;

    float4 v0 = xr[tid];
    float4 v1 = xr[tid + 256];
    float s  = v0.x + v0.y + v0.z + v0.w + v1.x + v1.y + v1.z + v1.w;
    float sq = v0.x*v0.x + v0.y*v0.y + v0.z*v0.z + v0.w*v0.w
             + v1.x*v1.x + v1.y*v1.y + v1.z*v1.z + v1.w*v1.w;

    __shared__ float rs[8], rq[8];
    #pragma unroll
    for (int o = 16; o > 0; o >>= 1) {
        s  += __shfl_xor_sync(0xffffffffu, s,  o);
        sq += __shfl_xor_sync(0xffffffffu, sq, o);
    }
    if ((tid & 31) == 0) { rs[tid >> 5] = s; rq[tid >> 5] = sq; }
    __syncthreads();
    float ts = 0.f, tq = 0.f;
    #pragma unroll
    for (int i = 0; i < 8; i++) { ts += rs[i]; tq += rq[i]; }

    float mean = ts * (1.0f / HH);
    float var  = tq * (1.0f / HH) - mean * mean;
    float rstd = rsqrtf(var + 1e-6f);

    yh[tid * 2 + 0]   = __floats2half2_rn((v0.x - mean) * rstd, (v0.y - mean) * rstd);
    yh[tid * 2 + 1]   = __floats2half2_rn((v0.z - mean) * rstd, (v0.w - mean) * rstd);
    yh[512 + tid * 2] = __floats2half2_rn((v1.x - mean) * rstd, (v1.y - mean) * rstd);
    yh[513 + tid * 2] = __floats2half2_rn((v1.z - mean) * rstd, (v1.w - mean) * rstd);
}

// ---------------------------------------------------------------------------
// Tiled transpose (TI in -> half out): out[c*ldo + r] = in[r*ldi + c]
// ---------------------------------------------------------------------------
template<typename TI>
__global__ void __launch_bounds__(256) transpose_kernel(
    const TI* __restrict__ in, __half* __restrict__ out,
    int ldi, int ldo, size_t sIz, size_t sOz)
{
    __shared__ float t[32][33];
    in  += (size_t)blockIdx.z * sIz;
    out += (size_t)blockIdx.z * sOz;
    int tx = threadIdx.x & 31, ty = threadIdx.x >> 5;   // 32 x 8
    int c = blockIdx.x * 32 + tx;
    int r = blockIdx.y * 32 + ty;
    #pragma unroll
    for (int j = 0; j < 4; j++) {
        float v;
        if (sizeof(TI) == 2) v = __half2float(((const __half*)in)[(size_t)(r + 8 * j) * ldi + c]);
        else                 v = ((const float*)in)[(size_t)(r + 8 * j) * ldi + c];
        t[ty + 8 * j][tx] = v;
    }
    __syncthreads();
    int co = blockIdx.y * 32 + tx;
    int ro = blockIdx.x * 32 + ty;
    #pragma unroll
    for (int j = 0; j < 4; j++)
        out[(size_t)(ro + 8 * j) * ldo + co] = __float2half_rn(t[tx][ty + 8 * j]);
}

// ---------------------------------------------------------------------------
// fp16 mma.sync NT GEMM: C[M,N] = A[M,K] @ B[N,K]^T (half, K-major).
// BM=BN=128, BK=64 (128B rows), double-buffered cp.async, ldmatrix fragments.
// Smem chunk swizzle: 16B chunk ch of row r stored at (ch ^ (r & 7)).
// Warp grid 2(M) x 4(N): warp tile 64x32.
// ---------------------------------------------------------------------------
#define BK 64
#define STAGE_BYTES 32768            // A 16KB + B 16KB
#define GEMM_DYN_SMEM (2 * STAGE_BYTES)

template<typename CT, bool CAUSAL, bool RES>
__global__ void __launch_bounds__(256, 2) hgemm(
    const __half* __restrict__ A, const __half* __restrict__ B,
    CT* __restrict__ C, const float* __restrict__ Resid,
    int K, int lda, int ldb, int ldc,
    size_t sAz, size_t sBz, size_t sCz)
{
    const int bx = blockIdx.x, by = blockIdx.y, bz = blockIdx.z;
    if (CAUSAL && bx > by) return;

    extern __shared__ char sm[];
    const uint32_t s0 = smem_u32(sm);

    const int tid = threadIdx.x;
    const int wid = tid >> 5, lane = tid & 31;
    const int wm = (wid & 1) * 64;
    const int wn = (wid >> 1) * 32;

    const __half* Ab = A + (size_t)bz * sAz + (size_t)(by * 128) * lda;
    const __half* Bb = B + (size_t)bz * sBz + (size_t)(bx * 128) * ldb;

    // cp.async mapping: row = tid/2 (0..127), 4 chunks of 16B each
    const int ldRow = tid >> 1;
    const int ldCh0 = (tid & 1) * 4;

    float acc[4][4][4];
    #pragma unroll
    for (int i = 0; i < 4; i++)
        #pragma unroll
        for (int j = 0; j < 4; j++)
            #pragma unroll
            for (int h = 0; h < 4; h++) acc[i][j][h] = 0.f;

    const int nk = K / BK;

    auto load_stage = [&](int kt, int st) {
        const int k0 = kt * BK;
        const uint32_t as = s0 + st * STAGE_BYTES;
        const uint32_t bs = as + 16384;
        const uint32_t rsw = (uint32_t)(ldRow & 7);
        #pragma unroll
        for (int i = 0; i < 4; i++) {
            const int ch = ldCh0 + i;
            const uint32_t off = (uint32_t)ldRow * 128 + (((uint32_t)ch ^ rsw) << 4);
            cp_async16(as + off, Ab + (size_t)ldRow * lda + k0 + ch * 8);
            cp_async16(bs + off, Bb + (size_t)ldRow * ldb + k0 + ch * 8);
        }
        asm volatile("cp.async.commit_group;" ::: "memory");
    };

    load_stage(0, 0);

    for (int kt = 0; kt < nk; kt++) {
        const int st = kt & 1;
        if (kt + 1 < nk) {
            load_stage(kt + 1, st ^ 1);
            asm volatile("cp.async.wait_group 1;" ::: "memory");
        } else {
            asm volatile("cp.async.wait_group 0;" ::: "memory");
        }
        __syncthreads();

        const uint32_t as = s0 + st * STAGE_BYTES;
        const uint32_t bs = as + 16384;
        const uint32_t rlow = (uint32_t)(lane & 7);
        const uint32_t r16  = (uint32_t)(lane & 15);

        #pragma unroll
        for (int ks = 0; ks < 4; ks++) {
            const uint32_t ch = (uint32_t)(ks * 2 + (lane >> 4));
            const uint32_t sw = ((ch ^ rlow) << 4);
            uint32_t a[4][4], b[4][2];
            #pragma unroll
            for (int mt = 0; mt < 4; mt++) {
                const uint32_t addr = as + (wm + mt * 16 + r16) * 128 + sw;
                ldmatrix_x4(a[mt], addr);
            }
            #pragma unroll
            for (int nb = 0; nb < 2; nb++) {
                uint32_t r[4];
                const uint32_t addr = bs + (wn + nb * 16 + r16) * 128 + sw;
                ldmatrix_x4(r, addr);
                b[2 * nb + 0][0] = r[0]; b[2 * nb + 0][1] = r[2];
                b[2 * nb + 1][0] = r[1]; b[2 * nb + 1][1] = r[3];
            }
            #pragma unroll
            for (int mt = 0; mt < 4; mt++)
                #pragma unroll
                for (int nt = 0; nt < 4; nt++)
                    mma_f16(acc[mt][nt], a[mt], b[nt]);
        }
        __syncthreads();
    }

    // epilogue
    const int qid = lane >> 2, tq = lane & 3;
    C += (size_t)bz * sCz;
    const int crow0 = by * 128 + wm;
    const int ccol0 = bx * 128 + wn;
    #pragma unroll
    for (int mt = 0; mt < 4; mt++) {
        #pragma unroll
        for (int h = 0; h < 2; h++) {
            const int row = crow0 + mt * 16 + qid + h * 8;
            CT* cr = C + (size_t)row * ldc;
            const float* rr = RES ? (Resid + (size_t)bz * sCz + (size_t)row * ldc) : nullptr;
            #pragma unroll
            for (int nt = 0; nt < 4; nt++) {
                const int col = ccol0 + nt * 8 + tq * 2;
                float vx = acc[mt][nt][2 * h + 0];
                float vy = acc[mt][nt][2 * h + 1];
                if (RES) {
                    const float2 rv = *(const float2*)(rr + col);
                    vx += rv.x; vy += rv.y;
                }
                if (sizeof(CT) == 2) {
                    *(__half2*)((__half*)cr + col) = __floats2half2_rn(vx, vy);
                } else {
                    *(float2*)((float*)cr + col) = make_float2(vx, vy);
                }
            }
        }
    }
}

// ---------------------------------------------------------------------------
// Causal softmax: fp32 scores in -> half probs out (zeros above diagonal)
// ---------------------------------------------------------------------------
__global__ void __launch_bounds__(256) softmax_kernel(
    const float* __restrict__ scores, __half* __restrict__ probs, float scale)
{
    const int r = blockIdx.x;
    const int b = blockIdx.y;
    const float* rin = scores + ((size_t)b * SS + r) * SS;
    __half* rout = probs + ((size_t)b * SS + r) * SS;
    const int len = r + 1;
    const int tid = threadIdx.x;

    __shared__ float buf[SS];
    __shared__ float red[8];

    float lmax = -1e30f;
    for (int t = tid; t < len; t += 256) {
        float v = rin[t] * scale;
        buf[t] = v;
        lmax = fmaxf(lmax, v);
    }
    #pragma unroll
    for (int o = 16; o > 0; o >>= 1)
        lmax = fmaxf(lmax, __shfl_xor_sync(0xffffffffu, lmax, o));
    if ((tid & 31) == 0) red[tid >> 5] = lmax;
    __syncthreads();
    float m = -1e30f;
    #pragma unroll
    for (int i = 0; i < 8; i++) m = fmaxf(m, red[i]);
    __syncthreads();

    float lsum = 0.f;
    for (int t = tid; t < len; t += 256) {
        float e = expf(buf[t] - m);
        buf[t] = e;
        lsum += e;
    }
    #pragma unroll
    for (int o = 16; o > 0; o >>= 1)
        lsum += __shfl_xor_sync(0xffffffffu, lsum, o);
    if ((tid & 31) == 0) red[tid >> 5] = lsum;
    __syncthreads();
    float tot = 0.f;
    #pragma unroll
    for (int i = 0; i < 8; i++) tot += red[i];
    const float inv = 1.0f / tot;

    for (int t = tid; t < len; t += 256) rout[t] = __float2half_rn(buf[t] * inv);
    const __half hz = __float2half_rn(0.f);
    for (int t = len + tid; t < SS; t += 256) rout[t] = hz;
}

// ---------------------------------------------------------------------------
// Launch
// ---------------------------------------------------------------------------
extern "C" void kernel_launch(void* const* d_in, const int* in_sizes, int n_in,
                              void* d_out, int out_size)
{
    (void)in_sizes; (void)n_in; (void)out_size;
    const float* x     = (const float*)d_in[0];   // (2, 4096, 2048)
    const float* qkvW  = (const float*)d_in[1];   // (2048, 6144)
    const float* oproj = (const float*)d_in[2];   // (2048, 2048)
    float* out = (float*)d_out;                   // (2, 4096, 2048)

    __half *xh, *qh, *ph, *ah, *qTh, *oTh, *vTh;
    float *sc;
    cudaGetSymbolAddress((void**)&xh,  g_xh);
    cudaGetSymbolAddress((void**)&qh,  g_qh);
    cudaGetSymbolAddress((void**)&sc,  g_sc);
    cudaGetSymbolAddress((void**)&ph,  g_ph);
    cudaGetSymbolAddress((void**)&ah,  g_ah);
    cudaGetSymbolAddress((void**)&qTh, g_qTh);
    cudaGetSymbolAddress((void**)&oTh, g_oTh);
    cudaGetSymbolAddress((void**)&vTh, g_vTh);

    cudaFuncSetAttribute(hgemm<__half, false, false>,
                         cudaFuncAttributeMaxDynamicSharedMemorySize, GEMM_DYN_SMEM);
    cudaFuncSetAttribute(hgemm<float, true, false>,
                         cudaFuncAttributeMaxDynamicSharedMemorySize, GEMM_DYN_SMEM);
    cudaFuncSetAttribute(hgemm<float, false, true>,
                         cudaFuncAttributeMaxDynamicSharedMemorySize, GEMM_DYN_SMEM);

    const int M = BB * SS;                 // 8192
    const float scale = 1.0f / sqrtf((float)DD);

    // 1) LayerNorm -> half
    ln_kernel<<<M, 256>>>(x, xh);

    // 2) Weight transposes -> half
    transpose_kernel<float><<<dim3(ND / 32, HH / 32, 1), 256>>>(qkvW, qTh, ND, HH, 0, 0);
    transpose_kernel<float><<<dim3(HH / 32, DD / 32, 1), 256>>>(oproj, oTh, HH, DD, 0, 0);

    // 3) QKV GEMM: xh[8192,2048] @ qTh[6144,2048]^T -> qh[8192,6144]
    hgemm<__half, false, false><<<dim3(ND / 128, M / 128, 1), 256, GEMM_DYN_SMEM>>>(
        xh, qTh, qh, nullptr, HH, HH, HH, ND, 0, 0, 0);

    // 4) V transpose: V half [4096,2048] (ld=6144) -> vTh [2048,4096]
    transpose_kernel<__half><<<dim3(DD / 32, SS / 32, BB), 256>>>(
        qh + 2 * DD, vTh, ND, SS, (size_t)SS * ND, (size_t)DD * SS);

    // 5) Scores = Q @ K^T (causal block-skip) -> fp32
    hgemm<float, true, false><<<dim3(SS / 128, SS / 128, BB), 256, GEMM_DYN_SMEM>>>(
        qh, qh + DD, sc, nullptr, DD, ND, ND, SS,
        (size_t)SS * ND, (size_t)SS * ND, (size_t)SS * SS);

    // 6) Causal softmax: fp32 -> half probs
    softmax_kernel<<<dim3(SS, BB), 256>>>(sc, ph, scale);

    // 7) Attn = P @ V^T -> half
    hgemm<__half, false, false><<<dim3(DD / 128, SS / 128, BB), 256, GEMM_DYN_SMEM>>>(
        ph, vTh, ah, nullptr, SS, SS, SS, DD,
        (size_t)SS * SS, (size_t)DD * SS, (size_t)SS * DD);

    // 8) Out = attn @ oTh^T + x  -> fp32
    hgemm<float, false, true><<<dim3(HH / 128, M / 128, 1), 256, GEMM_DYN_SMEM>>>(
        ah, oTh, out, x, DD, DD, DD, HH, 0, 0, 0);
}

// round 6
// speedup vs baseline: 5.8221x; 1.0707x over previous
#include <cuda_runtime.h>
#include <cuda_fp16.h>
#include <math.h>
#include <stdint.h>

// Problem constants
#define BB 2
#define SS 4096
#define HH 2048
#define DD 2048
#define ND 6144   // 3*D

// ---------------------------------------------------------------------------
// Scratch (allocation-free: __device__ globals)
// ---------------------------------------------------------------------------
__device__ __half g_xh [(size_t)BB * SS * HH];    //  32 MB  LN output
__device__ __half g_qh [(size_t)BB * SS * ND];    //  96 MB  QKV output (Q,K,V)
__device__ float  g_sc [(size_t)BB * SS * SS];    // 128 MB  scores (fp32)
__device__ __half g_ph [(size_t)BB * SS * SS];    //  64 MB  probs (half)
__device__ __half g_ah [(size_t)BB * SS * DD];    //  32 MB  attn out
__device__ __half g_qTh[(size_t)ND * HH];         //  24 MB  qkv weight^T
__device__ __half g_oTh[(size_t)HH * DD];         //   8 MB  o_proj^T
__device__ __half g_vTh[(size_t)BB * DD * SS];    //  32 MB  V^T

// ---------------------------------------------------------------------------
// Helpers
// ---------------------------------------------------------------------------
__device__ __forceinline__ uint32_t smem_u32(const void* p) {
    uint32_t a;
    asm("{ .reg .u64 t; cvta.to.shared.u64 t, %1; cvt.u32.u64 %0, t; }" : "=r"(a) : "l"(p));
    return a;
}

__device__ __forceinline__ void cp_async16(uint32_t smem, const void* glob) {
    asm volatile("cp.async.cg.shared.global [%0], [%1], 16;" :: "r"(smem), "l"(glob));
}

__device__ __forceinline__ void ldmatrix_x4(uint32_t* r, uint32_t addr) {
    asm volatile("ldmatrix.sync.aligned.m8n8.x4.shared.b16 {%0,%1,%2,%3}, [%4];"
                 : "=r"(r[0]), "=r"(r[1]), "=r"(r[2]), "=r"(r[3]) : "r"(addr));
}

__device__ __forceinline__ void mma_f16(float* c, const uint32_t* a, const uint32_t* b) {
    asm volatile(
        "mma.sync.aligned.m16n8k16.row.col.f32.f16.f16.f32 "
        "{%0,%1,%2,%3}, {%4,%5,%6,%7}, {%8,%9}, {%0,%1,%2,%3};"
        : "+f"(c[0]), "+f"(c[1]), "+f"(c[2]), "+f"(c[3])
        : "r"(a[0]), "r"(a[1]), "r"(a[2]), "r"(a[3]), "r"(b[0]), "r"(b[1]));
}

// ---------------------------------------------------------------------------
// LayerNorm: fp32 in -> half out
// ---------------------------------------------------------------------------
__global__ void __launch_bounds__(256) ln_kernel(const float* __restrict__ x,
                                                 __half* __restrict__ xh)
{
    int row = blockIdx.x;
    const float4* xr = (const float4*)(x + (size_t)row * HH);
    __half2* yh = (__half2*)(xh + (size_t)row * HH);
    int tid = threadIdx.x;

    float4 v0 = xr[tid];
    float4 v1 = xr[tid + 256];
    float s  = v0.x + v0.y + v0.z + v0.w + v1.x + v1.y + v1.z + v1.w;
    float sq = v0.x*v0.x + v0.y*v0.y + v0.z*v0.z + v0.w*v0.w
             + v1.x*v1.x + v1.y*v1.y + v1.z*v1.z + v1.w*v1.w;

    __shared__ float rs[8], rq[8];
    #pragma unroll
    for (int o = 16; o > 0; o >>= 1) {
        s  += __shfl_xor_sync(0xffffffffu, s,  o);
        sq += __shfl_xor_sync(0xffffffffu, sq, o);
    }
    if ((tid & 31) == 0) { rs[tid >> 5] = s; rq[tid >> 5] = sq; }
    __syncthreads();
    float ts = 0.f, tq = 0.f;
    #pragma unroll
    for (int i = 0; i < 8; i++) { ts += rs[i]; tq += rq[i]; }

    float mean = ts * (1.0f / HH);
    float var  = tq * (1.0f / HH) - mean * mean;
    float rstd = rsqrtf(var + 1e-6f);

    yh[tid * 2 + 0]   = __floats2half2_rn((v0.x - mean) * rstd, (v0.y - mean) * rstd);
    yh[tid * 2 + 1]   = __floats2half2_rn((v0.z - mean) * rstd, (v0.w - mean) * rstd);
    yh[512 + tid * 2] = __floats2half2_rn((v1.x - mean) * rstd, (v1.y - mean) * rstd);
    yh[513 + tid * 2] = __floats2half2_rn((v1.z - mean) * rstd, (v1.w - mean) * rstd);
}

// ---------------------------------------------------------------------------
// Tiled transpose (TI in -> half out): out[c*ldo + r] = in[r*ldi + c]
// ---------------------------------------------------------------------------
template<typename TI>
__global__ void __launch_bounds__(256) transpose_kernel(
    const TI* __restrict__ in, __half* __restrict__ out,
    int ldi, int ldo, size_t sIz, size_t sOz)
{
    __shared__ float t[32][33];
    in  += (size_t)blockIdx.z * sIz;
    out += (size_t)blockIdx.z * sOz;
    int tx = threadIdx.x & 31, ty = threadIdx.x >> 5;   // 32 x 8
    int c = blockIdx.x * 32 + tx;
    int r = blockIdx.y * 32 + ty;
    #pragma unroll
    for (int j = 0; j < 4; j++) {
        float v;
        if (sizeof(TI) == 2) v = __half2float(((const __half*)in)[(size_t)(r + 8 * j) * ldi + c]);
        else                 v = ((const float*)in)[(size_t)(r + 8 * j) * ldi + c];
        t[ty + 8 * j][tx] = v;
    }
    __syncthreads();
    int co = blockIdx.y * 32 + tx;
    int ro = blockIdx.x * 32 + ty;
    #pragma unroll
    for (int j = 0; j < 4; j++)
        out[(size_t)(ro + 8 * j) * ldo + co] = __float2half_rn(t[tx][ty + 8 * j]);
}

// ---------------------------------------------------------------------------
// fp16 mma.sync NT GEMM: C[M,N] = A[M,K] @ B[N,K]^T (half, K-major).
// BM=128, BN=256, BK=64, 3-stage cp.async ring, 8 warps of 64x64 warp tiles.
// Smem rows are 128B, chunk swizzle (ch ^ (r&7)).
//   CAUSAL : skip output blocks entirely above the diagonal (scores)
//   KCAUS  : limit K loop to the diagonal (PV: A is lower-triangular)
// ---------------------------------------------------------------------------
#define BK 64
#define STAGE_BYTES 49152            // A 16KB + B 32KB
#define NSTAGE 3
#define GEMM_DYN_SMEM (NSTAGE * STAGE_BYTES)   // 147456

template<typename CT, bool CAUSAL, bool KCAUS, bool RES>
__global__ void __launch_bounds__(256, 1) hgemm(
    const __half* __restrict__ A, const __half* __restrict__ B,
    CT* __restrict__ C, const float* __restrict__ Resid,
    int K, int lda, int ldb, int ldc,
    size_t sAz, size_t sBz, size_t sCz)
{
    const int bx = blockIdx.x, by = blockIdx.y, bz = blockIdx.z;
    if (CAUSAL && bx * 256 > by * 128 + 127) return;

    extern __shared__ char sm[];
    const uint32_t s0 = smem_u32(sm);

    const int tid = threadIdx.x;
    const int wid = tid >> 5, lane = tid & 31;
    const int wm = (wid & 1) * 64;       // 2 warps along M
    const int wn = (wid >> 1) * 64;      // 4 warps along N

    const __half* Ab = A + (size_t)bz * sAz + (size_t)(by * 128) * lda;
    const __half* Bb = B + (size_t)bz * sBz + (size_t)(bx * 256) * ldb;

    // cp.async mapping: row = tid/2, chunks (tid&1)*4 .. +3
    const int ldRow = tid >> 1;
    const int ldCh0 = (tid & 1) * 4;

    float acc[4][8][4];
    #pragma unroll
    for (int i = 0; i < 4; i++)
        #pragma unroll
        for (int j = 0; j < 8; j++)
            #pragma unroll
            for (int h = 0; h < 4; h++) acc[i][j][h] = 0.f;

    int nk = K / BK;
    if (KCAUS) {
        int kmax = (by + 1) * 128;       // rows in this block see cols [0, kmax)
        if (kmax < K) nk = kmax / BK;
    }

    auto load_stage = [&](int kt, int st) {
        const int k0 = kt * BK;
        const uint32_t as = s0 + st * STAGE_BYTES;
        const uint32_t bs = as + 16384;
        const uint32_t rsw = (uint32_t)(ldRow & 7);
        #pragma unroll
        for (int i = 0; i < 4; i++) {
            const int ch = ldCh0 + i;
            const uint32_t off = (uint32_t)ldRow * 128 + (((uint32_t)ch ^ rsw) << 4);
            cp_async16(as + off, Ab + (size_t)ldRow * lda + k0 + ch * 8);
        }
        #pragma unroll
        for (int j = 0; j < 2; j++) {
            const int row = ldRow + j * 128;
            #pragma unroll
            for (int i = 0; i < 4; i++) {
                const int ch = ldCh0 + i;
                const uint32_t off = (uint32_t)row * 128 + (((uint32_t)ch ^ rsw) << 4);
                cp_async16(bs + off, Bb + (size_t)row * ldb + k0 + ch * 8);
            }
        }
        asm volatile("cp.async.commit_group;" ::: "memory");
    };

    // prologue: 2 stages in flight (nk >= 2 always here)
    load_stage(0, 0);
    load_stage(1, 1);

    const uint32_t rlow = (uint32_t)(lane & 7);
    const uint32_t r16  = (uint32_t)(lane & 15);

    int st = 0;
    for (int kt = 0; kt < nk; kt++) {
        if (kt + 1 < nk) {
            asm volatile("cp.async.wait_group 1;" ::: "memory");
        } else {
            asm volatile("cp.async.wait_group 0;" ::: "memory");
        }
        __syncthreads();

        // prefetch stage kt+2 (its smem slot was consumed at iter kt-1)
        if (kt + 2 < nk) {
            int st2 = st + 2; if (st2 >= NSTAGE) st2 -= NSTAGE;
            load_stage(kt + 2, st2);
        }

        const uint32_t as = s0 + st * STAGE_BYTES;
        const uint32_t bs = as + 16384;

        #pragma unroll
        for (int ks = 0; ks < 4; ks++) {
            const uint32_t ch = (uint32_t)(ks * 2 + (lane >> 4));
            const uint32_t sw = ((ch ^ rlow) << 4);
            uint32_t a[4][4], b[8][2];
            #pragma unroll
            for (int mt = 0; mt < 4; mt++) {
                const uint32_t addr = as + (wm + mt * 16 + r16) * 128 + sw;
                ldmatrix_x4(a[mt], addr);
            }
            #pragma unroll
            for (int nb = 0; nb < 4; nb++) {
                uint32_t r[4];
                const uint32_t addr = bs + (wn + nb * 16 + r16) * 128 + sw;
                ldmatrix_x4(r, addr);
                b[2 * nb + 0][0] = r[0]; b[2 * nb + 0][1] = r[2];
                b[2 * nb + 1][0] = r[1]; b[2 * nb + 1][1] = r[3];
            }
            #pragma unroll
            for (int mt = 0; mt < 4; mt++)
                #pragma unroll
                for (int nt = 0; nt < 8; nt++)
                    mma_f16(acc[mt][nt], a[mt], b[nt]);
        }
        __syncthreads();
        if (++st == NSTAGE) st = 0;
    }

    // epilogue
    const int qid = lane >> 2, tq = lane & 3;
    C += (size_t)bz * sCz;
    const int crow0 = by * 128 + wm;
    const int ccol0 = bx * 256 + wn;
    #pragma unroll
    for (int mt = 0; mt < 4; mt++) {
        #pragma unroll
        for (int h = 0; h < 2; h++) {
            const int row = crow0 + mt * 16 + qid + h * 8;
            CT* cr = C + (size_t)row * ldc;
            const float* rr = RES ? (Resid + (size_t)bz * sCz + (size_t)row * ldc) : nullptr;
            #pragma unroll
            for (int nt = 0; nt < 8; nt++) {
                const int col = ccol0 + nt * 8 + tq * 2;
                float vx = acc[mt][nt][2 * h + 0];
                float vy = acc[mt][nt][2 * h + 1];
                if (RES) {
                    const float2 rv = *(const float2*)(rr + col);
                    vx += rv.x; vy += rv.y;
                }
                if (sizeof(CT) == 2) {
                    *(__half2*)((__half*)cr + col) = __floats2half2_rn(vx, vy);
                } else {
                    *(float2*)((float*)cr + col) = make_float2(vx, vy);
                }
            }
        }
    }
}

// ---------------------------------------------------------------------------
// Causal softmax: fp32 scores in -> half probs out (zeros above diagonal)
// ---------------------------------------------------------------------------
__global__ void __launch_bounds__(256) softmax_kernel(
    const float* __restrict__ scores, __half* __restrict__ probs, float scale)
{
    const int r = blockIdx.x;
    const int b = blockIdx.y;
    const float* rin = scores + ((size_t)b * SS + r) * SS;
    __half* rout = probs + ((size_t)b * SS + r) * SS;
    const int len = r + 1;
    const int tid = threadIdx.x;

    __shared__ float buf[SS];
    __shared__ float red[8];

    float lmax = -1e30f;
    for (int t = tid; t < len; t += 256) {
        float v = rin[t] * scale;
        buf[t] = v;
        lmax = fmaxf(lmax, v);
    }
    #pragma unroll
    for (int o = 16; o > 0; o >>= 1)
        lmax = fmaxf(lmax, __shfl_xor_sync(0xffffffffu, lmax, o));
    if ((tid & 31) == 0) red[tid >> 5] = lmax;
    __syncthreads();
    float m = -1e30f;
    #pragma unroll
    for (int i = 0; i < 8; i++) m = fmaxf(m, red[i]);
    __syncthreads();

    float lsum = 0.f;
    for (int t = tid; t < len; t += 256) {
        float e = expf(buf[t] - m);
        buf[t] = e;
        lsum += e;
    }
    #pragma unroll
    for (int o = 16; o > 0; o >>= 1)
        lsum += __shfl_xor_sync(0xffffffffu, lsum, o);
    if ((tid & 31) == 0) red[tid >> 5] = lsum;
    __syncthreads();
    float tot = 0.f;
    #pragma unroll
    for (int i = 0; i < 8; i++) tot += red[i];
    const float inv = 1.0f / tot;

    for (int t = tid; t < len; t += 256) rout[t] = __float2half_rn(buf[t] * inv);
    const __half hz = __float2half_rn(0.f);
    for (int t = len + tid; t < SS; t += 256) rout[t] = hz;
}

// ---------------------------------------------------------------------------
// Launch
// ---------------------------------------------------------------------------
extern "C" void kernel_launch(void* const* d_in, const int* in_sizes, int n_in,
                              void* d_out, int out_size)
{
    (void)in_sizes; (void)n_in; (void)out_size;
    const float* x     = (const float*)d_in[0];   // (2, 4096, 2048)
    const float* qkvW  = (const float*)d_in[1];   // (2048, 6144)
    const float* oproj = (const float*)d_in[2];   // (2048, 2048)
    float* out = (float*)d_out;                   // (2, 4096, 2048)

    __half *xh, *qh, *ph, *ah, *qTh, *oTh, *vTh;
    float *sc;
    cudaGetSymbolAddress((void**)&xh,  g_xh);
    cudaGetSymbolAddress((void**)&qh,  g_qh);
    cudaGetSymbolAddress((void**)&sc,  g_sc);
    cudaGetSymbolAddress((void**)&ph,  g_ph);
    cudaGetSymbolAddress((void**)&ah,  g_ah);
    cudaGetSymbolAddress((void**)&qTh, g_qTh);
    cudaGetSymbolAddress((void**)&oTh, g_oTh);
    cudaGetSymbolAddress((void**)&vTh, g_vTh);

    cudaFuncSetAttribute(hgemm<__half, false, false, false>,
                         cudaFuncAttributeMaxDynamicSharedMemorySize, GEMM_DYN_SMEM);
    cudaFuncSetAttribute(hgemm<float, true, false, false>,
                         cudaFuncAttributeMaxDynamicSharedMemorySize, GEMM_DYN_SMEM);
    cudaFuncSetAttribute(hgemm<__half, false, true, false>,
                         cudaFuncAttributeMaxDynamicSharedMemorySize, GEMM_DYN_SMEM);
    cudaFuncSetAttribute(hgemm<float, false, false, true>,
                         cudaFuncAttributeMaxDynamicSharedMemorySize, GEMM_DYN_SMEM);

    const int M = BB * SS;                 // 8192
    const float scale = 1.0f / sqrtf((float)DD);

    // 1) LayerNorm -> half
    ln_kernel<<<M, 256>>>(x, xh);

    // 2) Weight transposes -> half
    transpose_kernel<float><<<dim3(ND / 32, HH / 32, 1), 256>>>(qkvW, qTh, ND, HH, 0, 0);
    transpose_kernel<float><<<dim3(HH / 32, DD / 32, 1), 256>>>(oproj, oTh, HH, DD, 0, 0);

    // 3) QKV GEMM: xh[8192,2048] @ qTh[6144,2048]^T -> qh[8192,6144]
    hgemm<__half, false, false, false><<<dim3(ND / 256, M / 128, 1), 256, GEMM_DYN_SMEM>>>(
        xh, qTh, qh, nullptr, HH, HH, HH, ND, 0, 0, 0);

    // 4) V transpose: V half [4096,2048] (ld=6144) -> vTh [2048,4096]
    transpose_kernel<__half><<<dim3(DD / 32, SS / 32, BB), 256>>>(
        qh + 2 * DD, vTh, ND, SS, (size_t)SS * ND, (size_t)DD * SS);

    // 5) Scores = Q @ K^T (causal block-skip) -> fp32
    hgemm<float, true, false, false><<<dim3(SS / 256, SS / 128, BB), 256, GEMM_DYN_SMEM>>>(
        qh, qh + DD, sc, nullptr, DD, ND, ND, SS,
        (size_t)SS * ND, (size_t)SS * ND, (size_t)SS * SS);

    // 6) Causal softmax: fp32 -> half probs
    softmax_kernel<<<dim3(SS, BB), 256>>>(sc, ph, scale);

    // 7) Attn = P @ V^T -> half (K-causal: skip zero columns of P)
    hgemm<__half, false, true, false><<<dim3(DD / 256, SS / 128, BB), 256, GEMM_DYN_SMEM>>>(
        ph, vTh, ah, nullptr, SS, SS, SS, DD,
        (size_t)SS * SS, (size_t)DD * SS, (size_t)SS * DD);

    // 8) Out = attn @ oTh^T + x  -> fp32
    hgemm<float, false, false, true><<<dim3(HH / 256, M / 128, 1), 256, GEMM_DYN_SMEM>>>(
        ah, oTh, out, x, DD, DD, DD, HH, 0, 0, 0);
}